// round 5
// baseline (speedup 1.0000x reference)
#include <cuda_runtime.h>
#include <cstdint>

// RNN_16801912062326: leaky-ReLU Elman RNN scan.
// B=256, T=512, DIN=128, H=256, DOUT=64, fp32.
//
// 64 clusters x 2 CTAs; each cluster owns 4 batch rows for all 512 steps.
// Each CTA computes half of H (128 j) and half of DOUT (32).
// GEMM1 (384x128 per CTA, x4 batches) uses packed fma.rn.f32x2:
//   thread tile = 4j x 4b x 48k (warp = one K-chunk, lanes = j-quads).
//   Half of each thread's W slice (24k x 4j = 96 regs) is register-resident;
//   the other half is read from SMEM as float4 j-quads.
//   Activations are stored DUPLICATED ((c,c) pairs) so LDS.128 yields two
//   f32x2 operands directly.
// 8-way cross-warp K-split -> partial reduce in SMEM, epilogue by 128 threads.
// Hidden halves exchanged via DSMEM dup-stores + one barrier.cluster per step.

#define RNN_B    256
#define RNN_T    512
#define RNN_DIN  128
#define RNN_H    256
#define RNN_DOUT 64
#define BT       4
#define THREADS  256

// ---- SMEM layout (floats) ----
constexpr int WS_PITCH   = 132;                   // multiple of 4 (16B-aligned quads)
constexpr int WS_ROWS    = 192;                   // smem half: 24 k per chunk x 8 chunks
constexpr int WS_FLOATS  = WS_ROWS * WS_PITCH;    // 25344
constexpr int COMB_FLOATS= 2 * 384 * 8;           // ping-pong, duplicated: [2][384][8]
constexpr int PART_FLOATS  = 8 * 4 * 32 * 4;      // GEMM1 partials [kc][i][jq] float4 = 4096
constexpr int PART2_FLOATS = 4 * 16 * 16 * 2;     // GEMM2 partials [b][kc2][jp2] u64 = 2048

constexpr int OFF_W     = 0;
constexpr int OFF_COMB  = OFF_W + WS_FLOATS;           // 25344
constexpr int OFF_PART  = OFF_COMB + COMB_FLOATS;      // 31488
constexpr int OFF_PART2 = OFF_PART + PART_FLOATS;      // 35584
constexpr int OFF_BIH   = OFF_PART2 + PART2_FLOATS;    // 37632
constexpr int OFF_BHO   = OFF_BIH + 128;               // 37760
constexpr int SMEM_FLOATS = OFF_BHO + 32;              // 37792
constexpr int SMEM_BYTES  = SMEM_FLOATS * 4;           // 151168 B

static_assert(OFF_COMB % 4 == 0, "16B align");
static_assert(OFF_PART % 4 == 0, "16B align");
static_assert(OFF_PART2 % 4 == 0, "16B align");

__device__ __forceinline__ void cluster_sync_inline() {
    asm volatile("barrier.cluster.arrive.aligned;\n\t"
                 "barrier.cluster.wait.aligned;" ::: "memory");
}

__device__ __forceinline__ void ffma2(uint64_t& acc, uint64_t a, uint64_t b) {
    asm("fma.rn.f32x2 %0, %1, %2, %0;" : "+l"(acc) : "l"(a), "l"(b));
}
__device__ __forceinline__ uint64_t pk2(float lo, float hi) {
    return (uint64_t)__float_as_uint(lo) | ((uint64_t)__float_as_uint(hi) << 32);
}
__device__ __forceinline__ float lo32(uint64_t v) { return __uint_as_float((uint32_t)v); }
__device__ __forceinline__ float hi32(uint64_t v) { return __uint_as_float((uint32_t)(v >> 32)); }

__global__ void __launch_bounds__(THREADS, 1) __cluster_dims__(2, 1, 1)
rnn_scan_kernel(const float* __restrict__ inputs,   // [B, T, DIN]
                const float* __restrict__ x0,       // [B, DOUT]
                const float* __restrict__ h0,       // [B, H]
                const float* __restrict__ W_ih,     // [H, DIN+H] = [256, 384]
                const float* __restrict__ b_ih,     // [H]
                const float* __restrict__ W_ho,     // [DOUT, H] = [64, 256]
                const float* __restrict__ b_ho,     // [DOUT]
                float* __restrict__ xout,           // [B, T+1, DOUT]
                float* __restrict__ hout)           // [B, T+1, H]
{
    extern __shared__ float smem[];
    const int tid  = threadIdx.x;
    const int rank = blockIdx.x & 1;
    const int cid  = blockIdx.x >> 1;
    const int b0   = cid * BT;

    float*    Ws    = smem + OFF_W;       // [192][132]: smem-half of W_ih^T
    float*    combA = smem + OFF_COMB;    // [2][384][8] dup: rows 0..127 u, 128..383 h
    float*    part  = smem + OFF_PART;    // [8][4][32] float4
    uint64_t* part2 = (uint64_t*)(smem + OFF_PART2); // [4][16][16] u64
    float*    bihs  = smem + OFF_BIH;     // [128]
    float*    bhos  = smem + OFF_BHO;     // [32]

    // ---------------- setup ----------------
    // SMEM half of W_ih^T: rows (kc*24 + kk-24) for kk in [24,48), j local 0..127.
    {
        const int jbase = rank * 128;
        for (int idx = tid; idx < 128 * 96; idx += THREADS) {
            int j  = idx / 96;
            int k4 = idx % 96;
            float4 v = *(const float4*)&W_ih[(size_t)(jbase + j) * 384 + 4 * k4];
            float vv[4] = {v.x, v.y, v.z, v.w};
            #pragma unroll
            for (int i = 0; i < 4; i++) {
                int k  = 4 * k4 + i;
                int kc = k / 48, kk = k % 48;
                if (kk >= 24)
                    Ws[(kc * 24 + (kk - 24)) * WS_PITCH + j] = vv[i];
            }
        }
    }
    if (tid < 128) bihs[tid] = b_ih[rank * 128 + tid];
    if (tid < 32)  bhos[tid] = b_ho[rank * 32 + tid];

    // GEMM1 register-resident half: thread (kc = tid>>5, jq = tid&31),
    // j = 4*jq .. 4*jq+3, k = kc*48 + kk for kk in [0,24).
    const int kc = tid >> 5;          // 0..7, == warp id
    const int jq = tid & 31;
    uint64_t w2reg[48];
    {
        const size_t jg0 = (size_t)(rank * 128 + 4 * jq);
        const int kb = kc * 48;
        #pragma unroll
        for (int kk = 0; kk < 24; kk++) {
            int k = kb + kk;
            w2reg[2*kk + 0] = pk2(W_ih[(jg0 + 0) * 384 + k], W_ih[(jg0 + 1) * 384 + k]);
            w2reg[2*kk + 1] = pk2(W_ih[(jg0 + 2) * 384 + k], W_ih[(jg0 + 3) * 384 + k]);
        }
    }

    // GEMM2 weights: thread (kc2 = tid>>4, jp2 = tid&15) owns j-pair (2*jp2, 2*jp2+1)
    // for k in [kc2*16, kc2*16+16).
    const int kc2 = tid >> 4;         // 0..15
    const int jp2 = tid & 15;
    uint64_t wreg2[16];
    {
        const size_t r0 = (size_t)(rank * 32 + 2 * jp2) * 256;
        #pragma unroll
        for (int kk = 0; kk < 16; kk++) {
            int k = kc2 * 16 + kk;
            wreg2[kk] = pk2(W_ho[r0 + k], W_ho[r0 + 256 + k]);
        }
    }

    // h0 -> comb buffer 0 (duplicated) + hout t=0
    {
        uint64_t* c64 = (uint64_t*)combA;
        for (int idx = tid; idx < RNN_H * BT; idx += THREADS) {
            int b  = idx >> 8;
            int jg = idx & 255;
            float v = h0[(size_t)(b0 + b) * RNN_H + jg];
            c64[(128 + jg) * 4 + b] = pk2(v, v);
            hout[(size_t)(b0 + b) * (RNN_T + 1) * RNN_H + jg] = v;
        }
    }
    // x0 -> xout t=0
    for (int idx = tid; idx < RNN_DOUT * BT; idx += THREADS) {
        int b  = idx >> 6;
        int jg = idx & 63;
        xout[(size_t)(b0 + b) * (RNN_T + 1) * RNN_DOUT + jg] =
            x0[(size_t)(b0 + b) * RNN_DOUT + jg];
    }
    // u_0 -> comb buffer 0 (duplicated)
    {
        int bb = tid >> 6;
        int kk = (tid & 63) * 2;
        float2 u = *(const float2*)&inputs[((size_t)(b0 + bb) * RNN_T + 0) * RNN_DIN + kk];
        uint64_t* c64 = (uint64_t*)combA;
        c64[kk * 4 + bb]       = pk2(u.x, u.x);
        c64[(kk + 1) * 4 + bb] = pk2(u.y, u.y);
    }
    __syncthreads();
    cluster_sync_inline();

    // DSMEM peer base for combA
    uint32_t comb_local_u32 = (uint32_t)__cvta_generic_to_shared(combA);
    uint32_t comb_peer_u32;
    {
        uint32_t peer = rank ^ 1;
        asm("mapa.shared::cluster.u32 %0, %1, %2;"
            : "=r"(comb_peer_u32) : "r"(comb_local_u32), "r"(peer));
    }

    const int ubb = tid >> 6;
    const int ukk = (tid & 63) * 2;
    const int ej  = tid;              // epilogue1 j (tid<128)
    const int ei  = ej & 3, ejq = ej >> 2;
    const int j2  = tid & 31, eb = tid >> 5;   // epilogue2 (tid<128)

    const size_t hrow = (size_t)(RNN_T + 1) * RNN_H;
    const size_t xrow = (size_t)(RNN_T + 1) * RNN_DOUT;
    const int kb = kc * 48;

    for (int t = 0; t < RNN_T; t++) {
        const int p = t & 1;
        const float* combp = combA + p * 3072;
        float*       combn = combA + (p ^ 1) * 3072;
        uint64_t*    combn64 = (uint64_t*)combn;

        // prefetch u_{t+1}
        float2 unext = make_float2(0.f, 0.f);
        if (t + 1 < RNN_T)
            unext = *(const float2*)&inputs[((size_t)(b0 + ubb) * RNN_T + (t + 1)) * RNN_DIN + ukk];

        // ---- GEMM1: 4j x 4b x 48k per thread, packed f32x2 ----
        uint64_t acc[8];  // [b*2 + pair]; lanes = (j0,j1) or (j2,j3)
        #pragma unroll
        for (int i = 0; i < 8; i++) acc[i] = 0;

        {
            const float* crow = combp + kb * 8;
            // register-W half: kk in [0,24)
            #pragma unroll
            for (int kk = 0; kk < 24; kk++) {
                ulonglong2 q01 = *(const ulonglong2*)(crow + kk * 8);
                ulonglong2 q23 = *(const ulonglong2*)(crow + kk * 8 + 4);
                uint64_t w0 = w2reg[2*kk], w1 = w2reg[2*kk + 1];
                ffma2(acc[0], w0, q01.x); ffma2(acc[1], w1, q01.x);
                ffma2(acc[2], w0, q01.y); ffma2(acc[3], w1, q01.y);
                ffma2(acc[4], w0, q23.x); ffma2(acc[5], w1, q23.x);
                ffma2(acc[6], w0, q23.y); ffma2(acc[7], w1, q23.y);
            }
            // smem-W half: kk in [24,48)
            const float* wrow = Ws + (kc * 24) * WS_PITCH + 4 * jq;
            #pragma unroll
            for (int kk = 0; kk < 24; kk++) {
                ulonglong2 wq = *(const ulonglong2*)(wrow + kk * WS_PITCH);
                ulonglong2 q01 = *(const ulonglong2*)(crow + (24 + kk) * 8);
                ulonglong2 q23 = *(const ulonglong2*)(crow + (24 + kk) * 8 + 4);
                ffma2(acc[0], wq.x, q01.x); ffma2(acc[1], wq.y, q01.x);
                ffma2(acc[2], wq.x, q01.y); ffma2(acc[3], wq.y, q01.y);
                ffma2(acc[4], wq.x, q23.x); ffma2(acc[5], wq.y, q23.x);
                ffma2(acc[6], wq.x, q23.y); ffma2(acc[7], wq.y, q23.y);
            }
        }

        // partial stores: part[kc][i][jq] = float4 over b, for i = j&3
        {
            float4 s0, s1, s2, s3;
            s0 = make_float4(lo32(acc[0]), lo32(acc[2]), lo32(acc[4]), lo32(acc[6]));
            s1 = make_float4(hi32(acc[0]), hi32(acc[2]), hi32(acc[4]), hi32(acc[6]));
            s2 = make_float4(lo32(acc[1]), lo32(acc[3]), lo32(acc[5]), lo32(acc[7]));
            s3 = make_float4(hi32(acc[1]), hi32(acc[3]), hi32(acc[5]), hi32(acc[7]));
            float4* pb = (float4*)part + kc * 128 + jq;
            pb[0]  = s0;
            pb[32] = s1;
            pb[64] = s2;
            pb[96] = s3;
        }
        __syncthreads();

        // ---- epilogue1 (tid<128): reduce 8 chunks, bias, leaky, publish h ----
        if (tid < 128) {
            float bias = bihs[ej];
            float4 s = make_float4(bias, bias, bias, bias);
            const float4* pb = (const float4*)part + ei * 32 + ejq;
            #pragma unroll
            for (int c = 0; c < 8; c++) {
                float4 v = pb[c * 128];
                s.x += v.x; s.y += v.y; s.z += v.z; s.w += v.w;
            }
            s.x = s.x >= 0.f ? s.x : 0.01f * s.x;
            s.y = s.y >= 0.f ? s.y : 0.01f * s.y;
            s.z = s.z >= 0.f ? s.z : 0.01f * s.z;
            s.w = s.w >= 0.f ? s.w : 0.01f * s.w;

            const int jg = rank * 128 + ej;
            uint64_t d0 = pk2(s.x, s.x), d1 = pk2(s.y, s.y);
            uint64_t d2 = pk2(s.z, s.z), d3 = pk2(s.w, s.w);
            // local next-buffer (duplicated)
            uint64_t* dst = combn64 + (128 + jg) * 4;
            dst[0] = d0; dst[1] = d1; dst[2] = d2; dst[3] = d3;
            // peer next-buffer (DSMEM, duplicated)
            uint32_t pa = comb_peer_u32 +
                          (uint32_t)((p ^ 1) * 12288 + (128 + jg) * 32);
            asm volatile("st.shared::cluster.b64 [%0], %1;"      :: "r"(pa),      "l"(d0) : "memory");
            asm volatile("st.shared::cluster.b64 [%0], %1;"      :: "r"(pa + 8),  "l"(d1) : "memory");
            asm volatile("st.shared::cluster.b64 [%0], %1;"      :: "r"(pa + 16), "l"(d2) : "memory");
            asm volatile("st.shared::cluster.b64 [%0], %1;"      :: "r"(pa + 24), "l"(d3) : "memory");
            // global h output, row t+1
            hout[(size_t)(b0 + 0) * hrow + (size_t)(t + 1) * RNN_H + jg] = s.x;
            hout[(size_t)(b0 + 1) * hrow + (size_t)(t + 1) * RNN_H + jg] = s.y;
            hout[(size_t)(b0 + 2) * hrow + (size_t)(t + 1) * RNN_H + jg] = s.z;
            hout[(size_t)(b0 + 3) * hrow + (size_t)(t + 1) * RNN_H + jg] = s.w;
        }

        // u_{t+1} into next buffer (duplicated; u-region disjoint from h-region)
        if (t + 1 < RNN_T) {
            combn64[ukk * 4 + ubb]       = pk2(unext.x, unext.x);
            combn64[(ukk + 1) * 4 + ubb] = pk2(unext.y, unext.y);
        }

        cluster_sync_inline();   // publishes both h halves + u for step t+1

        // ---- GEMM2: 2j x 4b x 16k per thread, packed f32x2 ----
        {
            uint64_t a2[4] = {0, 0, 0, 0};
            const float* hrow_s = combn + (128 + kc2 * 16) * 8;
            #pragma unroll
            for (int kk = 0; kk < 16; kk++) {
                ulonglong2 q01 = *(const ulonglong2*)(hrow_s + kk * 8);
                ulonglong2 q23 = *(const ulonglong2*)(hrow_s + kk * 8 + 4);
                uint64_t w = wreg2[kk];
                ffma2(a2[0], w, q01.x);
                ffma2(a2[1], w, q01.y);
                ffma2(a2[2], w, q23.x);
                ffma2(a2[3], w, q23.y);
            }
            // part2[b][kc2][jp2]
            #pragma unroll
            for (int b = 0; b < 4; b++)
                part2[b * 256 + kc2 * 16 + jp2] = a2[b];
        }
        __syncthreads();

        // ---- epilogue2 (tid<128): reduce 16 chunks, bias, store x ----
        if (tid < 128) {
            float s = bhos[j2];
            const float* p2f = (const float*)part2;
            const int base = (eb * 256 + (j2 >> 1)) * 2 + (j2 & 1);
            #pragma unroll
            for (int c = 0; c < 16; c++)
                s += p2f[base + c * 32];
            xout[(size_t)(b0 + eb) * xrow + (size_t)(t + 1) * RNN_DOUT + rank * 32 + j2] = s;
        }
        // next step's part/part2 writes are ordered by the barriers inside it.
    }
}

extern "C" void kernel_launch(void* const* d_in, const int* in_sizes, int n_in,
                              void* d_out, int out_size) {
    (void)in_sizes; (void)n_in; (void)out_size;
    const float* inputs = (const float*)d_in[0];
    const float* x0     = (const float*)d_in[1];
    const float* h0     = (const float*)d_in[2];
    const float* W_ih   = (const float*)d_in[3];
    const float* b_ih   = (const float*)d_in[4];
    const float* W_ho   = (const float*)d_in[5];
    const float* b_ho   = (const float*)d_in[6];

    float* xout = (float*)d_out;                                   // [B, T+1, DOUT]
    float* hout = xout + (size_t)RNN_B * (RNN_T + 1) * RNN_DOUT;   // [B, T+1, H]

    cudaFuncSetAttribute(rnn_scan_kernel,
                         cudaFuncAttributeMaxDynamicSharedMemorySize, SMEM_BYTES);

    rnn_scan_kernel<<<128, THREADS, SMEM_BYTES>>>(
        inputs, x0, h0, W_ih, b_ih, W_ho, b_ho, xout, hout);
}